// round 2
// baseline (speedup 1.0000x reference)
#include <cuda_runtime.h>

#define HD 64
#define NB 32
#define NN 1024
#define BN_TOT (NB*NN)      // 32768
#define NA_TOT 16384

// scratch (allocation-free rule: __device__ globals)
__device__ float d_xb[BN_TOT*HD];   // xl1 + b2
__device__ float d_g [BN_TOT*HD];   // h @ W2^T
__device__ float d_A [BN_TOT*HD];   // scan input transform, [t][b][j]
__device__ float d_Y8[NA_TOT*8];
__device__ float d_ge[NB*HD];

__device__ __forceinline__ void ffma2(float2 &c, const float2 a, const float2 b) {
    asm("fma.rn.f32x2 %0, %1, %2, %0;"
        : "+l"(reinterpret_cast<unsigned long long&>(c))
        : "l"(reinterpret_cast<const unsigned long long&>(a)),
          "l"(reinterpret_cast<const unsigned long long&>(b)));
}

// ---------------- K1: xb = x@W1^T + b1 + b2 ; h = relu(xb) ----------------
__global__ void k_init(const float* __restrict__ x, const float* __restrict__ W1,
                       const float* __restrict__ b1, const float* __restrict__ b2,
                       float* __restrict__ hout) {
    int idx = blockIdx.x * 256 + threadIdx.x;          // 8192 blocks -> 2097152 exact
    int i = idx >> 6, j = idx & 63;
    float2 xv = ((const float2*)x)[i];
    float v = fmaf(xv.x, W1[2*j], fmaf(xv.y, W1[2*j+1], b1[j])) + b2[j];
    d_xb[idx] = v;
    hout[idx] = fmaxf(v, 0.f);
}

// ---------------- K2: out = in @ W^T (+bias), mode0 -> d_g, mode1 -> d_A permuted ----------------
__global__ void k_small(const float* __restrict__ in, const float* __restrict__ W,
                        const float* __restrict__ bA, const float* __restrict__ bB,
                        int mode) {
    __shared__ float Wt[64*64];
    __shared__ __align__(16) float hs[16][64];
    __shared__ float bs[64];
    int tid = threadIdx.x;
    for (int idx = tid; idx < 4096; idx += 256)
        Wt[(idx & 63) * 64 + (idx >> 6)] = W[idx];      // W[j][k] -> Wt[k][j]
    if (tid < 64) bs[tid] = mode ? (bA[tid] + bB[tid]) : 0.0f;
    int i0 = blockIdx.x * 16;
    for (int idx = tid; idx < 1024; idx += 256)
        ((float*)hs)[idx] = in[i0 * 64 + idx];
    __syncthreads();
    int j = tid & 63, rb = tid >> 6;
    float* outp = mode ? d_A : d_g;
    #pragma unroll
    for (int rr = 0; rr < 4; ++rr) {
        int r = rb * 4 + rr;
        float a0 = 0, a1 = 0, a2 = 0, a3 = 0;
        #pragma unroll
        for (int k = 0; k < 64; k += 4) {
            float4 c = *(const float4*)&hs[r][k];
            a0 = fmaf(c.x, Wt[(k+0)*64+j], a0);
            a1 = fmaf(c.y, Wt[(k+1)*64+j], a1);
            a2 = fmaf(c.z, Wt[(k+2)*64+j], a2);
            a3 = fmaf(c.w, Wt[(k+3)*64+j], a3);
        }
        float acc = (a0 + a1) + (a2 + a3) + bs[j];
        int i = i0 + r;
        int o = mode ? (((i & 1023) * 32 + (i >> 10)) * 64 + j) : (i * 64 + j);
        outp[o] = acc;
    }
}

// ---------------- K3: h = relu(xb + adj @ g) ----------------
__global__ void __launch_bounds__(256) k_gnn(const float* __restrict__ adj,
                                             float* __restrict__ hout) {
    int bb = blockIdx.y;
    int rt = blockIdx.x;                 // 16 row tiles of 64
    const float* Ab = adj + ((size_t)bb << 20) + ((size_t)rt << 16);
    const float* Gb = d_g + ((size_t)bb << 16);
    __shared__ float As[2][64][33];
    __shared__ __align__(16) float Bs[2][32][64];
    int tid = threadIdx.x;
    int tx = tid & 15, ty = tid >> 4;
    float2 acc[4][2];
    #pragma unroll
    for (int r = 0; r < 4; ++r) { acc[r][0] = make_float2(0,0); acc[r][1] = make_float2(0,0); }

    auto load = [&](int buf, int kt) {
        #pragma unroll
        for (int u = 0; u < 2; ++u) {
            int s = tid * 2 + u;
            int ar = s >> 3, ac = (s & 7) * 4;
            float4 av = *(const float4*)(Ab + ar * 1024 + kt * 32 + ac);
            As[buf][ar][ac+0] = av.x; As[buf][ar][ac+1] = av.y;
            As[buf][ar][ac+2] = av.z; As[buf][ar][ac+3] = av.w;
            int br = s >> 4, bc = (s & 15) * 4;
            *(float4*)&Bs[buf][br][bc] = *(const float4*)(Gb + (kt * 32 + br) * 64 + bc);
        }
    };
    load(0, 0);
    __syncthreads();
    for (int kt = 0; kt < 32; ++kt) {
        int cur = kt & 1;
        if (kt + 1 < 32) load(cur ^ 1, kt + 1);
        #pragma unroll
        for (int kk = 0; kk < 32; ++kk) {
            float4 bv = *(const float4*)&Bs[cur][kk][tx * 4];
            float2 b01 = make_float2(bv.x, bv.y);
            float2 b23 = make_float2(bv.z, bv.w);
            #pragma unroll
            for (int r = 0; r < 4; ++r) {
                float a = As[cur][ty * 4 + r][kk];
                float2 ad = make_float2(a, a);
                ffma2(acc[r][0], ad, b01);
                ffma2(acc[r][1], ad, b23);
            }
        }
        __syncthreads();
    }
    #pragma unroll
    for (int r = 0; r < 4; ++r) {
        size_t row = ((size_t)bb << 10) + (rt << 6) + ty * 4 + r;
        size_t o = row * 64 + tx * 4;
        float4 xb = *(const float4*)&d_xb[o];
        float4 res;
        res.x = fmaxf(xb.x + acc[r][0].x, 0.f);
        res.y = fmaxf(xb.y + acc[r][0].y, 0.f);
        res.z = fmaxf(xb.z + acc[r][1].x, 0.f);
        res.w = fmaxf(xb.w + acc[r][1].y, 0.f);
        *(float4*)&hout[o] = res;
    }
}

// ---------------- K4: sequential 2-layer tanh RNN scan, 1 block per batch ----------------
__global__ void __launch_bounds__(128) k_scan(const float* __restrict__ Whh0,
        const float* __restrict__ Wih1, const float* __restrict__ Whh1,
        const float* __restrict__ bih1, const float* __restrict__ bhh1,
        const float* __restrict__ Wt6, const float* __restrict__ bt6) {
    extern __shared__ float sm[];
    float* W0t = sm;                 // 4096 (Whh0^T: [k][j])
    float* W1i = sm + 4096;          // Wih1^T
    float* W1h = sm + 8192;          // Whh1^T
    float* c0s = sm + 12288;         // [2][64]
    float* c1s = c0s + 128;          // [2][64]
    float* p1s = c1s + 128;          // [64]
    float* Asb = p1s + 64;           // [2][64]
    float* bsum = Asb + 128;         // [64]
    int b = blockIdx.x, tid = threadIdx.x;
    for (int idx = tid; idx < 4096; idx += 128) {
        int j = idx >> 6, k = idx & 63;
        W0t[k * 64 + j] = Whh0[idx];
        W1i[k * 64 + j] = Wih1[idx];
        W1h[k * 64 + j] = Whh1[idx];
    }
    if (tid < 64) {
        bsum[tid] = bih1[tid] + bhh1[tid];
        c0s[tid] = 0.f; c1s[tid] = 0.f;
        Asb[tid] = d_A[b * 64 + tid];
    }
    __syncthreads();
    int pc = 0;
    for (int t = 0; t < 1024; ++t) {
        if (tid < 64) {
            // layer 0: c0' = tanh(A_t + c0 @ Whh0^T)
            int j = tid;
            float a0 = Asb[pc * 64 + j], a1 = 0, a2 = 0, a3 = 0;
            const float* c = c0s + pc * 64;
            #pragma unroll
            for (int k = 0; k < 64; k += 4) {
                float4 cv = *(const float4*)(c + k);
                a0 = fmaf(cv.x, W0t[(k+0)*64+j], a0);
                a1 = fmaf(cv.y, W0t[(k+1)*64+j], a1);
                a2 = fmaf(cv.z, W0t[(k+2)*64+j], a2);
                a3 = fmaf(cv.w, W0t[(k+3)*64+j], a3);
            }
            c0s[(pc ^ 1) * 64 + j] = tanhf((a0 + a1) + (a2 + a3));
        } else {
            // parallel: p1 = (bih1+bhh1) + c1 @ Whh1^T ; prefetch A_{t+1}
            int j = tid - 64;
            float pf = (t + 1 < 1024) ? d_A[((t + 1) * 32 + b) * 64 + j] : 0.f;
            float a0 = bsum[j], a1 = 0, a2 = 0, a3 = 0;
            const float* c = c1s + pc * 64;
            #pragma unroll
            for (int k = 0; k < 64; k += 4) {
                float4 cv = *(const float4*)(c + k);
                a0 = fmaf(cv.x, W1h[(k+0)*64+j], a0);
                a1 = fmaf(cv.y, W1h[(k+1)*64+j], a1);
                a2 = fmaf(cv.z, W1h[(k+2)*64+j], a2);
                a3 = fmaf(cv.w, W1h[(k+3)*64+j], a3);
            }
            p1s[j] = (a0 + a1) + (a2 + a3);
            Asb[(pc ^ 1) * 64 + j] = pf;
        }
        __syncthreads();
        if (tid < 64) {
            // layer 1: c1' = tanh(p1 + c0' @ Wih1^T)
            int j = tid;
            float a0 = p1s[j], a1 = 0, a2 = 0, a3 = 0;
            const float* c = c0s + (pc ^ 1) * 64;
            #pragma unroll
            for (int k = 0; k < 64; k += 4) {
                float4 cv = *(const float4*)(c + k);
                a0 = fmaf(cv.x, W1i[(k+0)*64+j], a0);
                a1 = fmaf(cv.y, W1i[(k+1)*64+j], a1);
                a2 = fmaf(cv.z, W1i[(k+2)*64+j], a2);
                a3 = fmaf(cv.w, W1i[(k+3)*64+j], a3);
            }
            c1s[(pc ^ 1) * 64 + j] = tanhf((a0 + a1) + (a2 + a3));
        }
        __syncthreads();
        pc ^= 1;
    }
    if (tid < 64) {
        int j = tid;
        float acc = bt6[j];
        #pragma unroll 8
        for (int k = 0; k < 64; ++k) acc = fmaf(c1s[pc * 64 + k], Wt6[j * 64 + k], acc);
        d_ge[b * 64 + j] = acc;
    }
}

// ---------------- K5: gather + R + Y8 ----------------
__global__ void k_r(const int* __restrict__ label, const int* __restrict__ actions,
                    const float* __restrict__ x, float* __restrict__ Rout) {
    int a = blockIdx.x * 256 + threadIdx.x;            // 64 blocks -> 16384 exact
    int b = a >> 9;
    int i0 = actions[2 * a], i1 = actions[2 * a + 1];
    const int* lb = label + (b << 10);
    int a0 = lb[i0];
    int a1 = lb[i1];
    int li = lb[(i0 + 1023) & 1023];
    int ri = lb[(i1 + 1) & 1023];
    int off = b << 10;
    const float2* xv = (const float2*)x;
    float2 y0 = xv[a0 + off], y1 = xv[a1 + off], y2 = xv[li + off], y3 = xv[ri + off];
    float d02x = y0.x - y2.x, d02y = y0.y - y2.y;
    float d13x = y1.x - y3.x, d13y = y1.y - y3.y;
    float d12x = y1.x - y2.x, d12y = y1.y - y2.y;
    float d03x = y0.x - y3.x, d03y = y0.y - y3.y;
    float R = sqrtf(fmaf(d02x, d02x, d02y * d02y)) + sqrtf(fmaf(d13x, d13x, d13y * d13y))
            - sqrtf(fmaf(d12x, d12x, d12y * d12y)) - sqrtf(fmaf(d03x, d03x, d03y * d03y));
    Rout[a] = R;
    float4* Y = (float4*)(d_Y8 + a * 8);
    Y[0] = make_float4(y0.x, y0.y, y1.x, y1.y);
    Y[1] = make_float4(y2.x, y2.y, y3.x, y3.y);
}

// ---------------- K6: feat + Q ----------------
__global__ void k_q(const float* __restrict__ WL, const float* __restrict__ bL,
                    const float* __restrict__ Wt5, const float* __restrict__ bt5,
                    const float* __restrict__ R, float* __restrict__ Q) {
    __shared__ float ges[64], WLs[512], bLs[64], w5[65];
    int b = blockIdx.x, a = threadIdx.x;               // 32 blocks x 512
    if (a < 64) { ges[a] = d_ge[b * 64 + a]; bLs[a] = bL[a]; w5[a] = Wt5[a]; }
    if (a == 64) w5[64] = Wt5[64];
    WLs[a] = WL[a];
    __syncthreads();
    int ba = b * 512 + a;
    float4 y0 = *(const float4*)&d_Y8[ba * 8];
    float4 y1 = *(const float4*)&d_Y8[ba * 8 + 4];
    float y[8] = {y0.x, y0.y, y0.z, y0.w, y1.x, y1.y, y1.z, y1.w};
    float q = 0.f;
    #pragma unroll 8
    for (int j = 0; j < 64; ++j) {
        float f = ges[j] + bLs[j];
        #pragma unroll
        for (int m = 0; m < 8; ++m) f = fmaf(y[m], WLs[j * 8 + m], f);
        q = fmaf(fmaxf(f, 0.f), w5[j], q);
    }
    Q[ba] = fmaf(R[ba], w5[64], q) + bt5[0];
}

extern "C" void kernel_launch(void* const* d_in, const int* in_sizes, int n_in,
                              void* d_out, int out_size) {
    const float* adj  = (const float*)d_in[0];
    const float* x    = (const float*)d_in[1];
    const int*  label = (const int*)  d_in[2];
    const int*  acts  = (const int*)  d_in[3];
    const float* W1   = (const float*)d_in[4];
    const float* b1   = (const float*)d_in[5];
    const float* W2   = (const float*)d_in[6];
    const float* b2   = (const float*)d_in[7];
    const float* Wih0 = (const float*)d_in[8];
    const float* bih0 = (const float*)d_in[9];
    const float* Whh0 = (const float*)d_in[10];
    const float* bhh0 = (const float*)d_in[11];
    const float* Wih1 = (const float*)d_in[12];
    const float* bih1 = (const float*)d_in[13];
    const float* Whh1 = (const float*)d_in[14];
    const float* bhh1 = (const float*)d_in[15];
    const float* Wt6  = (const float*)d_in[16];
    const float* bt6  = (const float*)d_in[17];
    const float* WL   = (const float*)d_in[18];
    const float* bL   = (const float*)d_in[19];
    const float* Wt5  = (const float*)d_in[20];
    const float* bt5  = (const float*)d_in[21];

    float* out  = (float*)d_out;
    float* Rout = out;                      // 16384
    float* hout = out + 16384;              // 32768*64
    float* Qout = out + 16384 + BN_TOT * HD;

    cudaFuncSetAttribute(k_scan, cudaFuncAttributeMaxDynamicSharedMemorySize, 51200);

    // GNN step 1 (h=0 -> h = relu(xl1 + b2)), also stash xb = xl1 + b2
    k_init<<<8192, 256>>>(x, W1, b1, b2, hout);
    // GNN steps 2,3: g = h@W2^T ; h = relu(xb + adj@g)
    for (int it = 0; it < 2; ++it) {
        k_small<<<2048, 256>>>(hout, W2, b2, b2, 0);
        k_gnn<<<dim3(16, 32), 256>>>(adj, hout);
    }
    // scan input transform A[t][b][j] = h@Wih0^T + bih0 + bhh0 (permuted)
    k_small<<<2048, 256>>>(hout, Wih0, bih0, bhh0, 1);
    // sequential scan -> ge
    k_scan<<<32, 128, 51200>>>(Whh0, Wih1, Whh1, bih1, bhh1, Wt6, bt6);
    // R + Y gather
    k_r<<<64, 256>>>(label, acts, x, Rout);
    // feat + Q
    k_q<<<32, 512>>>(WL, bL, Wt5, bt5, Rout, Qout);
}

// round 3
// speedup vs baseline: 1.0011x; 1.0011x over previous
#include <cuda_runtime.h>

#define HD 64
#define NB 32
#define NN 1024
#define BN_TOT (NB*NN)      // 32768
#define NA_TOT 16384

// scratch (allocation-free rule: __device__ globals)
__device__ float d_xb[BN_TOT*HD];   // xl1 + b2
__device__ float d_g [BN_TOT*HD];   // h @ W2^T
__device__ float d_A [BN_TOT*HD];   // scan input transform, [t][b][j]
__device__ float d_Y8[NA_TOT*8];
__device__ float d_ge[NB*HD];

__device__ __forceinline__ void ffma2(float2 &c, const float2 a, const float2 b) {
    asm("fma.rn.f32x2 %0, %1, %2, %0;"
        : "+l"(reinterpret_cast<unsigned long long&>(c))
        : "l"(reinterpret_cast<const unsigned long long&>(a)),
          "l"(reinterpret_cast<const unsigned long long&>(b)));
}

// ---------------- K1: xb = x@W1^T + b1 + b2 ; h = relu(xb) ----------------
__global__ void k_init(const float* __restrict__ x, const float* __restrict__ W1,
                       const float* __restrict__ b1, const float* __restrict__ b2,
                       float* __restrict__ hout) {
    int idx = blockIdx.x * 256 + threadIdx.x;          // 8192 blocks -> 2097152 exact
    int i = idx >> 6, j = idx & 63;
    float2 xv = ((const float2*)x)[i];
    float v = fmaf(xv.x, W1[2*j], fmaf(xv.y, W1[2*j+1], b1[j])) + b2[j];
    d_xb[idx] = v;
    hout[idx] = fmaxf(v, 0.f);
}

// ---------------- K2: out = in @ W^T (+bias), mode0 -> d_g, mode1 -> d_A permuted ----------------
__global__ void k_small(const float* __restrict__ in, const float* __restrict__ W,
                        const float* __restrict__ bA, const float* __restrict__ bB,
                        int mode) {
    __shared__ float Wt[64*64];
    __shared__ __align__(16) float hs[16][64];
    __shared__ float bs[64];
    int tid = threadIdx.x;
    for (int idx = tid; idx < 4096; idx += 256)
        Wt[(idx & 63) * 64 + (idx >> 6)] = W[idx];      // W[j][k] -> Wt[k][j]
    if (tid < 64) bs[tid] = mode ? (bA[tid] + bB[tid]) : 0.0f;
    int i0 = blockIdx.x * 16;
    for (int idx = tid; idx < 1024; idx += 256)
        ((float*)hs)[idx] = in[i0 * 64 + idx];
    __syncthreads();
    int j = tid & 63, rb = tid >> 6;
    float* outp = mode ? d_A : d_g;
    #pragma unroll
    for (int rr = 0; rr < 4; ++rr) {
        int r = rb * 4 + rr;
        float a0 = 0, a1 = 0, a2 = 0, a3 = 0;
        #pragma unroll
        for (int k = 0; k < 64; k += 4) {
            float4 c = *(const float4*)&hs[r][k];
            a0 = fmaf(c.x, Wt[(k+0)*64+j], a0);
            a1 = fmaf(c.y, Wt[(k+1)*64+j], a1);
            a2 = fmaf(c.z, Wt[(k+2)*64+j], a2);
            a3 = fmaf(c.w, Wt[(k+3)*64+j], a3);
        }
        float acc = (a0 + a1) + (a2 + a3) + bs[j];
        int i = i0 + r;
        int o = mode ? (((i & 1023) * 32 + (i >> 10)) * 64 + j) : (i * 64 + j);
        outp[o] = acc;
    }
}

// ---------------- K3: h = relu(xb + adj @ g) ----------------
__global__ void __launch_bounds__(256) k_gnn(const float* __restrict__ adj,
                                             float* __restrict__ hout) {
    int bb = blockIdx.y;
    int rt = blockIdx.x;                 // 16 row tiles of 64
    const float* Ab = adj + ((size_t)bb << 20) + ((size_t)rt << 16);
    const float* Gb = d_g + ((size_t)bb << 16);
    __shared__ float As[2][64][33];
    __shared__ __align__(16) float Bs[2][32][64];
    int tid = threadIdx.x;
    int tx = tid & 15, ty = tid >> 4;
    float2 acc[4][2];
    #pragma unroll
    for (int r = 0; r < 4; ++r) { acc[r][0] = make_float2(0,0); acc[r][1] = make_float2(0,0); }

    auto load = [&](int buf, int kt) {
        #pragma unroll
        for (int u = 0; u < 2; ++u) {
            int s = tid * 2 + u;
            int ar = s >> 3, ac = (s & 7) * 4;
            float4 av = *(const float4*)(Ab + ar * 1024 + kt * 32 + ac);
            As[buf][ar][ac+0] = av.x; As[buf][ar][ac+1] = av.y;
            As[buf][ar][ac+2] = av.z; As[buf][ar][ac+3] = av.w;
            int br = s >> 4, bc = (s & 15) * 4;
            *(float4*)&Bs[buf][br][bc] = *(const float4*)(Gb + (kt * 32 + br) * 64 + bc);
        }
    };
    load(0, 0);
    __syncthreads();
    for (int kt = 0; kt < 32; ++kt) {
        int cur = kt & 1;
        if (kt + 1 < 32) load(cur ^ 1, kt + 1);
        #pragma unroll
        for (int kk = 0; kk < 32; ++kk) {
            float4 bv = *(const float4*)&Bs[cur][kk][tx * 4];
            float2 b01 = make_float2(bv.x, bv.y);
            float2 b23 = make_float2(bv.z, bv.w);
            #pragma unroll
            for (int r = 0; r < 4; ++r) {
                float a = As[cur][ty * 4 + r][kk];
                float2 ad = make_float2(a, a);
                ffma2(acc[r][0], ad, b01);
                ffma2(acc[r][1], ad, b23);
            }
        }
        __syncthreads();
    }
    #pragma unroll
    for (int r = 0; r < 4; ++r) {
        size_t row = ((size_t)bb << 10) + (rt << 6) + ty * 4 + r;
        size_t o = row * 64 + tx * 4;
        float4 xb = *(const float4*)&d_xb[o];
        float4 res;
        res.x = fmaxf(xb.x + acc[r][0].x, 0.f);
        res.y = fmaxf(xb.y + acc[r][0].y, 0.f);
        res.z = fmaxf(xb.z + acc[r][1].x, 0.f);
        res.w = fmaxf(xb.w + acc[r][1].y, 0.f);
        *(float4*)&hout[o] = res;
    }
}

// ---------------- K4: sequential 2-layer tanh RNN scan, 1 block per batch ----------------
__global__ void __launch_bounds__(128) k_scan(const float* __restrict__ Whh0,
        const float* __restrict__ Wih1, const float* __restrict__ Whh1,
        const float* __restrict__ bih1, const float* __restrict__ bhh1,
        const float* __restrict__ Wt6, const float* __restrict__ bt6) {
    extern __shared__ float sm[];
    float* W0t = sm;                 // 4096 (Whh0^T: [k][j])
    float* W1i = sm + 4096;          // Wih1^T
    float* W1h = sm + 8192;          // Whh1^T
    float* c0s = sm + 12288;         // [2][64]
    float* c1s = c0s + 128;          // [2][64]
    float* p1s = c1s + 128;          // [64]
    float* Asb = p1s + 64;           // [2][64]
    float* bsum = Asb + 128;         // [64]
    int b = blockIdx.x, tid = threadIdx.x;
    for (int idx = tid; idx < 4096; idx += 128) {
        int j = idx >> 6, k = idx & 63;
        W0t[k * 64 + j] = Whh0[idx];
        W1i[k * 64 + j] = Wih1[idx];
        W1h[k * 64 + j] = Whh1[idx];
    }
    if (tid < 64) {
        bsum[tid] = bih1[tid] + bhh1[tid];
        c0s[tid] = 0.f; c1s[tid] = 0.f;
        Asb[tid] = d_A[b * 64 + tid];
    }
    __syncthreads();
    int pc = 0;
    for (int t = 0; t < 1024; ++t) {
        if (tid < 64) {
            // layer 0: c0' = tanh(A_t + c0 @ Whh0^T)
            int j = tid;
            float a0 = Asb[pc * 64 + j], a1 = 0, a2 = 0, a3 = 0;
            const float* c = c0s + pc * 64;
            #pragma unroll
            for (int k = 0; k < 64; k += 4) {
                float4 cv = *(const float4*)(c + k);
                a0 = fmaf(cv.x, W0t[(k+0)*64+j], a0);
                a1 = fmaf(cv.y, W0t[(k+1)*64+j], a1);
                a2 = fmaf(cv.z, W0t[(k+2)*64+j], a2);
                a3 = fmaf(cv.w, W0t[(k+3)*64+j], a3);
            }
            c0s[(pc ^ 1) * 64 + j] = tanhf((a0 + a1) + (a2 + a3));
        } else {
            // parallel: p1 = (bih1+bhh1) + c1 @ Whh1^T ; prefetch A_{t+1}
            int j = tid - 64;
            float pf = (t + 1 < 1024) ? d_A[((t + 1) * 32 + b) * 64 + j] : 0.f;
            float a0 = bsum[j], a1 = 0, a2 = 0, a3 = 0;
            const float* c = c1s + pc * 64;
            #pragma unroll
            for (int k = 0; k < 64; k += 4) {
                float4 cv = *(const float4*)(c + k);
                a0 = fmaf(cv.x, W1h[(k+0)*64+j], a0);
                a1 = fmaf(cv.y, W1h[(k+1)*64+j], a1);
                a2 = fmaf(cv.z, W1h[(k+2)*64+j], a2);
                a3 = fmaf(cv.w, W1h[(k+3)*64+j], a3);
            }
            p1s[j] = (a0 + a1) + (a2 + a3);
            Asb[(pc ^ 1) * 64 + j] = pf;
        }
        __syncthreads();
        if (tid < 64) {
            // layer 1: c1' = tanh(p1 + c0' @ Wih1^T)
            int j = tid;
            float a0 = p1s[j], a1 = 0, a2 = 0, a3 = 0;
            const float* c = c0s + (pc ^ 1) * 64;
            #pragma unroll
            for (int k = 0; k < 64; k += 4) {
                float4 cv = *(const float4*)(c + k);
                a0 = fmaf(cv.x, W1i[(k+0)*64+j], a0);
                a1 = fmaf(cv.y, W1i[(k+1)*64+j], a1);
                a2 = fmaf(cv.z, W1i[(k+2)*64+j], a2);
                a3 = fmaf(cv.w, W1i[(k+3)*64+j], a3);
            }
            c1s[(pc ^ 1) * 64 + j] = tanhf((a0 + a1) + (a2 + a3));
        }
        __syncthreads();
        pc ^= 1;
    }
    if (tid < 64) {
        int j = tid;
        float acc = bt6[j];
        #pragma unroll 8
        for (int k = 0; k < 64; ++k) acc = fmaf(c1s[pc * 64 + k], Wt6[j * 64 + k], acc);
        d_ge[b * 64 + j] = acc;
    }
}

// ---------------- K5: gather + R + Y8 ----------------
__global__ void k_r(const int* __restrict__ label, const int* __restrict__ actions,
                    const float* __restrict__ x, float* __restrict__ Rout) {
    int a = blockIdx.x * 256 + threadIdx.x;            // 64 blocks -> 16384 exact
    int b = a >> 9;
    int i0 = actions[2 * a], i1 = actions[2 * a + 1];
    const int* lb = label + (b << 10);
    int a0 = lb[i0];
    int a1 = lb[i1];
    int li = lb[(i0 + 1023) & 1023];
    int ri = lb[(i1 + 1) & 1023];
    int off = b << 10;
    const float2* xv = (const float2*)x;
    float2 y0 = xv[a0 + off], y1 = xv[a1 + off], y2 = xv[li + off], y3 = xv[ri + off];
    float d02x = y0.x - y2.x, d02y = y0.y - y2.y;
    float d13x = y1.x - y3.x, d13y = y1.y - y3.y;
    float d12x = y1.x - y2.x, d12y = y1.y - y2.y;
    float d03x = y0.x - y3.x, d03y = y0.y - y3.y;
    float R = sqrtf(fmaf(d02x, d02x, d02y * d02y)) + sqrtf(fmaf(d13x, d13x, d13y * d13y))
            - sqrtf(fmaf(d12x, d12x, d12y * d12y)) - sqrtf(fmaf(d03x, d03x, d03y * d03y));
    Rout[a] = R;
    float4* Y = (float4*)(d_Y8 + a * 8);
    Y[0] = make_float4(y0.x, y0.y, y1.x, y1.y);
    Y[1] = make_float4(y2.x, y2.y, y3.x, y3.y);
}

// ---------------- K6: feat + Q ----------------
__global__ void k_q(const float* __restrict__ WL, const float* __restrict__ bL,
                    const float* __restrict__ Wt5, const float* __restrict__ bt5,
                    const float* __restrict__ R, float* __restrict__ Q) {
    __shared__ float ges[64], WLs[512], bLs[64], w5[65];
    int b = blockIdx.x, a = threadIdx.x;               // 32 blocks x 512
    if (a < 64) { ges[a] = d_ge[b * 64 + a]; bLs[a] = bL[a]; w5[a] = Wt5[a]; }
    if (a == 64) w5[64] = Wt5[64];
    WLs[a] = WL[a];
    __syncthreads();
    int ba = b * 512 + a;
    float4 y0 = *(const float4*)&d_Y8[ba * 8];
    float4 y1 = *(const float4*)&d_Y8[ba * 8 + 4];
    float y[8] = {y0.x, y0.y, y0.z, y0.w, y1.x, y1.y, y1.z, y1.w};
    float q = 0.f;
    #pragma unroll 8
    for (int j = 0; j < 64; ++j) {
        float f = ges[j] + bLs[j];
        #pragma unroll
        for (int m = 0; m < 8; ++m) f = fmaf(y[m], WLs[j * 8 + m], f);
        q = fmaf(fmaxf(f, 0.f), w5[j], q);
    }
    Q[ba] = fmaf(R[ba], w5[64], q) + bt5[0];
}

extern "C" void kernel_launch(void* const* d_in, const int* in_sizes, int n_in,
                              void* d_out, int out_size) {
    const float* adj  = (const float*)d_in[0];
    const float* x    = (const float*)d_in[1];
    const int*  label = (const int*)  d_in[2];
    const int*  acts  = (const int*)  d_in[3];
    const float* W1   = (const float*)d_in[4];
    const float* b1   = (const float*)d_in[5];
    const float* W2   = (const float*)d_in[6];
    const float* b2   = (const float*)d_in[7];
    const float* Wih0 = (const float*)d_in[8];
    const float* bih0 = (const float*)d_in[9];
    const float* Whh0 = (const float*)d_in[10];
    const float* bhh0 = (const float*)d_in[11];
    const float* Wih1 = (const float*)d_in[12];
    const float* bih1 = (const float*)d_in[13];
    const float* Whh1 = (const float*)d_in[14];
    const float* bhh1 = (const float*)d_in[15];
    const float* Wt6  = (const float*)d_in[16];
    const float* bt6  = (const float*)d_in[17];
    const float* WL   = (const float*)d_in[18];
    const float* bL   = (const float*)d_in[19];
    const float* Wt5  = (const float*)d_in[20];
    const float* bt5  = (const float*)d_in[21];

    float* out  = (float*)d_out;
    float* Rout = out;                      // 16384
    float* hout = out + 16384;              // 32768*64
    float* Qout = out + 16384 + BN_TOT * HD;

    cudaFuncSetAttribute(k_scan, cudaFuncAttributeMaxDynamicSharedMemorySize, 51200);

    // GNN step 1 (h=0 -> h = relu(xl1 + b2)), also stash xb = xl1 + b2
    k_init<<<8192, 256>>>(x, W1, b1, b2, hout);
    // GNN steps 2,3: g = h@W2^T ; h = relu(xb + adj@g)
    for (int it = 0; it < 2; ++it) {
        k_small<<<2048, 256>>>(hout, W2, b2, b2, 0);
        k_gnn<<<dim3(16, 32), 256>>>(adj, hout);
    }
    // scan input transform A[t][b][j] = h@Wih0^T + bih0 + bhh0 (permuted)
    k_small<<<2048, 256>>>(hout, Wih0, bih0, bhh0, 1);
    // sequential scan -> ge
    k_scan<<<32, 128, 51200>>>(Whh0, Wih1, Whh1, bih1, bhh1, Wt6, bt6);
    // R + Y gather
    k_r<<<64, 256>>>(label, acts, x, Rout);
    // feat + Q
    k_q<<<32, 512>>>(WL, bL, Wt5, bt5, Rout, Qout);
}

// round 5
// speedup vs baseline: 2.5460x; 2.5432x over previous
#include <cuda_runtime.h>
#include <cstdint>

#define HD 64
#define NB 32
#define BN_TOT (NB*1024)
#define NA_TOT 16384

__device__ float d_xb[BN_TOT*HD];
__device__ float d_g [BN_TOT*HD];   // g[b][node][hd], values pre-rounded to tf32
__device__ float d_A [BN_TOT*HD];   // [t][b][j]
__device__ float d_Y8[NA_TOT*8];
__device__ float d_ge[NB*HD];

__device__ __forceinline__ void ffma2(float2 &c, const float2 a, const float2 b) {
    asm("fma.rn.f32x2 %0, %1, %2, %0;"
        : "+l"(reinterpret_cast<unsigned long long&>(c))
        : "l"(reinterpret_cast<const unsigned long long&>(a)),
          "l"(reinterpret_cast<const unsigned long long&>(b)));
}
__device__ __forceinline__ uint32_t smem_u32(const void* p) {
    uint32_t a;
    asm("{ .reg .u64 t; cvta.to.shared.u64 t, %1; cvt.u32.u64 %0, t; }" : "=r"(a) : "l"(p));
    return a;
}
__device__ __forceinline__ void cp16(uint32_t dst, const void* src) {
    asm volatile("cp.async.cg.shared.global [%0], [%1], 16;" :: "r"(dst), "l"(src));
}
__device__ __forceinline__ uint32_t f2tf32(float x) {
    uint32_t r;
    asm("cvt.rna.tf32.f32 %0, %1;" : "=r"(r) : "f"(x));
    return r;
}
__device__ __forceinline__ void mma_tf32(float* d, uint32_t a0, uint32_t a1,
                                         uint32_t a2, uint32_t a3,
                                         uint32_t b0, uint32_t b1) {
    asm("mma.sync.aligned.m16n8k8.row.col.f32.tf32.tf32.f32 "
        "{%0,%1,%2,%3}, {%4,%5,%6,%7}, {%8,%9}, {%0,%1,%2,%3};"
        : "+f"(d[0]), "+f"(d[1]), "+f"(d[2]), "+f"(d[3])
        : "r"(a0), "r"(a1), "r"(a2), "r"(a3), "r"(b0), "r"(b1));
}
__device__ __forceinline__ float ftanh(float x) {
    float e = __expf(2.0f * x);
    return 1.0f - __fdividef(2.0f, e + 1.0f);
}

// ---- K1: xb = x@W1^T + b1 + b2 ; h = relu(xb) ----
__global__ void k_init(const float* __restrict__ x, const float* __restrict__ W1,
                       const float* __restrict__ b1, const float* __restrict__ b2,
                       float* __restrict__ hout) {
    int idx = blockIdx.x * 256 + threadIdx.x;
    int i = idx >> 6, j = idx & 63;
    float2 xv = ((const float2*)x)[i];
    float v = fmaf(xv.x, W1[2*j], fmaf(xv.y, W1[2*j+1], b1[j])) + b2[j];
    d_xb[idx] = v;
    hout[idx] = fmaxf(v, 0.f);
}

// ---- K2: mode0 -> d_g[b][node][hd] = tf32(in@W^T); mode1 -> d_A[t][b][j] = in@W^T + bA+bB ----
__global__ void __launch_bounds__(128) k_small(const float* __restrict__ in,
        const float* __restrict__ W, const float* __restrict__ bA,
        const float* __restrict__ bB, int mode) {
    __shared__ float hsT[64][36];
    __shared__ float Wt[64][68];
    __shared__ float bs[64];
    int tid = threadIdx.x;
    int i0 = blockIdx.x * 32;
    for (int idx = tid; idx < 4096; idx += 128)
        Wt[idx & 63][idx >> 6] = W[idx];
    if (mode && tid < 64) bs[tid] = bA[tid] + bB[tid];
    #pragma unroll
    for (int u = 0; u < 4; ++u) {
        int f = tid + 128 * u;
        int r = f >> 4, kc = (f & 15) * 4;
        float4 v = *(const float4*)&in[(i0 + r) * 64 + kc];
        hsT[kc+0][r] = v.x; hsT[kc+1][r] = v.y; hsT[kc+2][r] = v.z; hsT[kc+3][r] = v.w;
    }
    __syncthreads();
    int r4 = (tid & 7) * 4, j4 = (tid >> 3) * 4;
    float2 acc[4][2];
    #pragma unroll
    for (int rr = 0; rr < 4; ++rr) { acc[rr][0] = make_float2(0,0); acc[rr][1] = make_float2(0,0); }
    #pragma unroll 8
    for (int k = 0; k < 64; ++k) {
        float4 a = *(const float4*)&hsT[k][r4];
        float4 w = *(const float4*)&Wt[k][j4];
        float2 w01 = make_float2(w.x, w.y), w23 = make_float2(w.z, w.w);
        ffma2(acc[0][0], w01, make_float2(a.x, a.x));
        ffma2(acc[0][1], w23, make_float2(a.x, a.x));
        ffma2(acc[1][0], w01, make_float2(a.y, a.y));
        ffma2(acc[1][1], w23, make_float2(a.y, a.y));
        ffma2(acc[2][0], w01, make_float2(a.z, a.z));
        ffma2(acc[2][1], w23, make_float2(a.z, a.z));
        ffma2(acc[3][0], w01, make_float2(a.w, a.w));
        ffma2(acc[3][1], w23, make_float2(a.w, a.w));
    }
    int bb = i0 >> 10, rloc = (i0 & 1023) + r4;
    if (mode == 0) {
        #pragma unroll
        for (int rr = 0; rr < 4; ++rr) {
            float4 v;
            v.x = __uint_as_float(f2tf32(acc[rr][0].x));
            v.y = __uint_as_float(f2tf32(acc[rr][0].y));
            v.z = __uint_as_float(f2tf32(acc[rr][1].x));
            v.w = __uint_as_float(f2tf32(acc[rr][1].y));
            *(float4*)&d_g[(bb * 1024 + rloc + rr) * 64 + j4] = v;
        }
    } else {
        #pragma unroll
        for (int rr = 0; rr < 4; ++rr) {
            float4 v;
            v.x = acc[rr][0].x + bs[j4+0];
            v.y = acc[rr][0].y + bs[j4+1];
            v.z = acc[rr][1].x + bs[j4+2];
            v.w = acc[rr][1].y + bs[j4+3];
            *(float4*)&d_A[((rloc + rr) * 32 + bb) * 64 + j4] = v;
        }
    }
}

// ---- K3: h = relu(xb + adj@g) via mma.sync tf32 ----
#define APITCH 68
#define BPITCH 72
#define GSM_BYTES ((2*128*APITCH + 2*64*BPITCH) * 4)   // 106496

__global__ void __launch_bounds__(256, 2) k_gnn_mma(const float* __restrict__ adj,
                                                    float* __restrict__ hout) {
    extern __shared__ float sm[];
    float* As = sm;                          // [2][128][APITCH]
    float* Bs = sm + 2 * 128 * APITCH;       // [2][64][BPITCH]
    uint32_t sA = smem_u32(As), sB = smem_u32(Bs);
    int tid = threadIdx.x, lane = tid & 31, w = tid >> 5;
    int mt = blockIdx.x, bb = blockIdx.y;
    const float* Abase = adj + ((size_t)bb << 20) + ((size_t)mt << 17);
    const float* Bbase = d_g + ((size_t)bb << 16);

    float acc[8][4];
    #pragma unroll
    for (int j = 0; j < 8; ++j)
        #pragma unroll
        for (int q = 0; q < 4; ++q) acc[j][q] = 0.f;

    auto loadA = [&](int buf, int kt) {
        uint32_t dst = sA + buf * 128 * APITCH * 4;
        #pragma unroll
        for (int u = 0; u < 8; ++u) {
            int idx = tid + 256 * u;
            int fr = idx >> 4, fc = (idx & 15) * 4;
            cp16(dst + (fr * APITCH + fc) * 4, Abase + fr * 1024 + kt * 64 + fc);
        }
    };
    auto loadB = [&](int buf, int kt) {
        uint32_t dst = sB + buf * 64 * BPITCH * 4;
        #pragma unroll
        for (int u = 0; u < 4; ++u) {
            int idx = tid + 256 * u;
            int kr = idx >> 4, nc = (idx & 15) * 4;
            cp16(dst + (kr * BPITCH + nc) * 4, Bbase + (kt * 64 + kr) * 64 + nc);
        }
    };

    loadA(0, 0); loadB(0, 0);
    asm volatile("cp.async.commit_group;");

    int r = lane >> 2, c = lane & 3;
    for (int kt = 0; kt < 16; ++kt) {
        int buf = kt & 1;
        if (kt + 1 < 16) {
            loadA(buf ^ 1, kt + 1);
            loadB(buf ^ 1, kt + 1);
            asm volatile("cp.async.commit_group;");
            asm volatile("cp.async.wait_group 1;" ::: "memory");
        } else {
            asm volatile("cp.async.wait_group 0;" ::: "memory");
        }
        __syncthreads();
        const float* Ab = As + buf * 128 * APITCH + (16 * w) * APITCH;
        const float* Bb = Bs + buf * 64 * BPITCH;
        #pragma unroll
        for (int s = 0; s < 8; ++s) {
            int k8 = s * 8;
            uint32_t a0 = f2tf32(Ab[r * APITCH + k8 + c]);
            uint32_t a1 = f2tf32(Ab[(r + 8) * APITCH + k8 + c]);
            uint32_t a2 = f2tf32(Ab[r * APITCH + k8 + c + 4]);
            uint32_t a3 = f2tf32(Ab[(r + 8) * APITCH + k8 + c + 4]);
            #pragma unroll
            for (int j = 0; j < 8; ++j) {
                uint32_t b0 = __float_as_uint(Bb[(k8 + c) * BPITCH + 8 * j + r]);
                uint32_t b1 = __float_as_uint(Bb[(k8 + c + 4) * BPITCH + 8 * j + r]);
                mma_tf32(acc[j], a0, a1, a2, a3, b0, b1);
            }
        }
        __syncthreads();
    }

    size_t row0 = ((size_t)bb << 10) + ((size_t)mt << 7) + 16 * w;
    int c2 = (lane & 3) * 2;
    #pragma unroll
    for (int j = 0; j < 8; ++j) {
        int col = 8 * j + c2;
        size_t o0 = (row0 + r) * 64 + col;
        float2 xb0 = *(const float2*)&d_xb[o0];
        float2 h0;
        h0.x = fmaxf(xb0.x + acc[j][0], 0.f);
        h0.y = fmaxf(xb0.y + acc[j][1], 0.f);
        *(float2*)&hout[o0] = h0;
        size_t o1 = (row0 + r + 8) * 64 + col;
        float2 xb1 = *(const float2*)&d_xb[o1];
        float2 h1;
        h1.x = fmaxf(xb1.x + acc[j][2], 0.f);
        h1.y = fmaxf(xb1.y + acc[j][3], 0.f);
        *(float2*)&hout[o1] = h1;
    }
}

// ---- K4: pipelined scan, 1 barrier/step; warps0-1:c0[t], warps2-5:c1[t-1], warp6:prefetch ----
__global__ void __launch_bounds__(224, 1) k_scan2(const float* __restrict__ Whh0,
        const float* __restrict__ Wih1, const float* __restrict__ Whh1,
        const float* __restrict__ bih1, const float* __restrict__ bhh1,
        const float* __restrict__ Wt6, const float* __restrict__ bt6) {
    __shared__ float S[4][64];
    __shared__ float Abuf[8][64];
    __shared__ float bsum[64];
    int b = blockIdx.x, tid = threadIdx.x;
    for (int i = tid; i < 256; i += 224) ((float*)S)[i] = 0.f;
    if (tid < 64) bsum[tid] = bih1[tid] + bhh1[tid];

    float2 w[32];
    int part = 0, j0 = 0;
    float2 avreg = make_float2(0.f, 0.f);
    if (tid < 64) {
        int lane = tid & 31, wd = tid >> 5;
        int jp = wd * 16 + (lane & 15); part = lane >> 4; j0 = jp * 2;
        #pragma unroll
        for (int kk = 0; kk < 32; ++kk) {
            int k = part * 32 + kk;
            w[kk] = make_float2(Whh0[j0 * 64 + k], Whh0[(j0 + 1) * 64 + k]);
        }
    } else if (tid < 192) {
        int bt = tid - 64, lane = bt & 31, wd = bt >> 5;
        int jp = wd * 8 + (lane & 7); part = lane >> 3; j0 = jp * 2;
        #pragma unroll
        for (int kk = 0; kk < 32; ++kk) {
            int k = part * 32 + kk;
            const float* Ws = (k < 64) ? Wih1 : Whh1;
            int ko = k & 63;
            w[kk] = make_float2(Ws[j0 * 64 + ko], Ws[(j0 + 1) * 64 + ko]);
        }
    } else {
        int lane = tid - 192;
        #pragma unroll
        for (int u = 0; u < 4; ++u)
            *(float2*)&Abuf[u][lane * 2] = *(const float2*)&d_A[(u * 32 + b) * 64 + lane * 2];
        avreg = *(const float2*)&d_A[(4 * 32 + b) * 64 + lane * 2];
    }
    __syncthreads();

    int pc = 0;
    for (int t = 0; t <= 1024; ++t) {
        if (tid < 64) {
            if (t < 1024) {
                float2 a0 = {0,0}, a1 = {0,0}, a2 = {0,0}, a3 = {0,0};
                const float* c = &S[pc][part * 32];
                #pragma unroll
                for (int k4 = 0; k4 < 8; ++k4) {
                    float4 cv = *(const float4*)(c + k4 * 4);
                    ffma2(a0, w[k4*4+0], make_float2(cv.x, cv.x));
                    ffma2(a1, w[k4*4+1], make_float2(cv.y, cv.y));
                    ffma2(a2, w[k4*4+2], make_float2(cv.z, cv.z));
                    ffma2(a3, w[k4*4+3], make_float2(cv.w, cv.w));
                }
                float2 s;
                s.x = (a0.x + a1.x) + (a2.x + a3.x);
                s.y = (a0.y + a1.y) + (a2.y + a3.y);
                s.x += __shfl_xor_sync(0xffffffffu, s.x, 16);
                s.y += __shfl_xor_sync(0xffffffffu, s.y, 16);
                if (part == 0) {
                    float2 at = *(const float2*)&Abuf[t & 7][j0];
                    float2 rr;
                    rr.x = ftanh(s.x + at.x);
                    rr.y = ftanh(s.y + at.y);
                    *(float2*)&S[pc ^ 1][j0] = rr;
                }
            }
        } else if (tid < 192) {
            float2 a0 = {0,0}, a1 = {0,0}, a2 = {0,0}, a3 = {0,0};
            const float* c = (part < 2) ? &S[pc][(part & 1) * 32]
                                        : &S[2 + pc][(part & 1) * 32];
            #pragma unroll
            for (int k4 = 0; k4 < 8; ++k4) {
                float4 cv = *(const float4*)(c + k4 * 4);
                ffma2(a0, w[k4*4+0], make_float2(cv.x, cv.x));
                ffma2(a1, w[k4*4+1], make_float2(cv.y, cv.y));
                ffma2(a2, w[k4*4+2], make_float2(cv.z, cv.z));
                ffma2(a3, w[k4*4+3], make_float2(cv.w, cv.w));
            }
            float2 s;
            s.x = (a0.x + a1.x) + (a2.x + a3.x);
            s.y = (a0.y + a1.y) + (a2.y + a3.y);
            s.x += __shfl_xor_sync(0xffffffffu, s.x, 8);
            s.y += __shfl_xor_sync(0xffffffffu, s.y, 8);
            s.x += __shfl_xor_sync(0xffffffffu, s.x, 16);
            s.y += __shfl_xor_sync(0xffffffffu, s.y, 16);
            if (part == 0) {
                float2 bv = *(const float2*)&bsum[j0];
                float2 rr;
                if (t == 0) { rr.x = 0.f; rr.y = 0.f; }
                else { rr.x = ftanh(s.x + bv.x); rr.y = ftanh(s.y + bv.y); }
                *(float2*)&S[2 + (pc ^ 1)][j0] = rr;
            }
        } else {
            int lane = tid - 192;
            *(float2*)&Abuf[(t + 4) & 7][lane * 2] = avreg;
            int tt = t + 5;
            if (tt < 1024)
                avreg = *(const float2*)&d_A[(tt * 32 + b) * 64 + lane * 2];
        }
        __syncthreads();
        pc ^= 1;
    }
    if (tid < 64) {
        int j = tid;
        float acc = bt6[j];
        const float* cf = S[2 + pc];
        #pragma unroll 8
        for (int k = 0; k < 64; ++k) acc = fmaf(cf[k], Wt6[j * 64 + k], acc);
        d_ge[b * 64 + j] = acc;
    }
}

// ---- K5: gather + R + Y8 ----
__global__ void k_r(const int* __restrict__ label, const int* __restrict__ actions,
                    const float* __restrict__ x, float* __restrict__ Rout) {
    int a = blockIdx.x * 256 + threadIdx.x;
    int b = a >> 9;
    int i0 = actions[2 * a], i1 = actions[2 * a + 1];
    const int* lb = label + (b << 10);
    int a0 = lb[i0], a1 = lb[i1];
    int li = lb[(i0 + 1023) & 1023], ri = lb[(i1 + 1) & 1023];
    int off = b << 10;
    const float2* xv = (const float2*)x;
    float2 y0 = xv[a0 + off], y1 = xv[a1 + off], y2 = xv[li + off], y3 = xv[ri + off];
    float d02x = y0.x - y2.x, d02y = y0.y - y2.y;
    float d13x = y1.x - y3.x, d13y = y1.y - y3.y;
    float d12x = y1.x - y2.x, d12y = y1.y - y2.y;
    float d03x = y0.x - y3.x, d03y = y0.y - y3.y;
    float R = sqrtf(fmaf(d02x, d02x, d02y * d02y)) + sqrtf(fmaf(d13x, d13x, d13y * d13y))
            - sqrtf(fmaf(d12x, d12x, d12y * d12y)) - sqrtf(fmaf(d03x, d03x, d03y * d03y));
    Rout[a] = R;
    float4* Y = (float4*)(d_Y8 + a * 8);
    Y[0] = make_float4(y0.x, y0.y, y1.x, y1.y);
    Y[1] = make_float4(y2.x, y2.y, y3.x, y3.y);
}

// ---- K6: feat + Q ----
__global__ void k_q(const float* __restrict__ WL, const float* __restrict__ bL,
                    const float* __restrict__ Wt5, const float* __restrict__ bt5,
                    const float* __restrict__ R, float* __restrict__ Q) {
    __shared__ float ges[64], WLs[512], bLs[64], w5[65];
    int b = blockIdx.x, a = threadIdx.x;
    if (a < 64) { ges[a] = d_ge[b * 64 + a]; bLs[a] = bL[a]; w5[a] = Wt5[a]; }
    if (a == 64) w5[64] = Wt5[64];
    WLs[a] = WL[a];
    __syncthreads();
    int ba = b * 512 + a;
    float4 y0 = *(const float4*)&d_Y8[ba * 8];
    float4 y1 = *(const float4*)&d_Y8[ba * 8 + 4];
    float y[8] = {y0.x, y0.y, y0.z, y0.w, y1.x, y1.y, y1.z, y1.w};
    float q = 0.f;
    #pragma unroll 8
    for (int j = 0; j < 64; ++j) {
        float f = ges[j] + bLs[j];
        #pragma unroll
        for (int m = 0; m < 8; ++m) f = fmaf(y[m], WLs[j * 8 + m], f);
        q = fmaf(fmaxf(f, 0.f), w5[j], q);
    }
    Q[ba] = fmaf(R[ba], w5[64], q) + bt5[0];
}

extern "C" void kernel_launch(void* const* d_in, const int* in_sizes, int n_in,
                              void* d_out, int out_size) {
    const float* adj  = (const float*)d_in[0];
    const float* x    = (const float*)d_in[1];
    const int*  label = (const int*)  d_in[2];
    const int*  acts  = (const int*)  d_in[3];
    const float* W1   = (const float*)d_in[4];
    const float* b1   = (const float*)d_in[5];
    const float* W2   = (const float*)d_in[6];
    const float* b2   = (const float*)d_in[7];
    const float* Wih0 = (const float*)d_in[8];
    const float* bih0 = (const float*)d_in[9];
    const float* Whh0 = (const float*)d_in[10];
    const float* bhh0 = (const float*)d_in[11];
    const float* Wih1 = (const float*)d_in[12];
    const float* bih1 = (const float*)d_in[13];
    const float* Whh1 = (const float*)d_in[14];
    const float* bhh1 = (const float*)d_in[15];
    const float* Wt6  = (const float*)d_in[16];
    const float* bt6  = (const float*)d_in[17];
    const float* WL   = (const float*)d_in[18];
    const float* bL   = (const float*)d_in[19];
    const float* Wt5  = (const float*)d_in[20];
    const float* bt5  = (const float*)d_in[21];

    float* out  = (float*)d_out;
    float* Rout = out;
    float* hout = out + 16384;
    float* Qout = out + 16384 + BN_TOT * HD;

    cudaFuncSetAttribute(k_gnn_mma, cudaFuncAttributeMaxDynamicSharedMemorySize, GSM_BYTES);

    k_init<<<8192, 256>>>(x, W1, b1, b2, hout);
    for (int it = 0; it < 2; ++it) {
        k_small<<<1024, 128>>>(hout, W2, b2, b2, 0);
        k_gnn_mma<<<dim3(8, 32), 256, GSM_BYTES>>>(adj, hout);
    }
    k_small<<<1024, 128>>>(hout, Wih0, bih0, bhh0, 1);
    k_scan2<<<32, 224>>>(Whh0, Wih1, Whh1, bih1, bhh1, Wt6, bt6);
    k_r<<<64, 256>>>(label, acts, x, Rout);
    k_q<<<32, 512>>>(WL, bL, Wt5, bt5, Rout, Qout);
}

// round 6
// speedup vs baseline: 2.6368x; 1.0357x over previous
#include <cuda_runtime.h>
#include <cuda_bf16.h>
#include <cstdint>

#define HD 64
#define NB 32
#define BN_TOT (NB*1024)
#define NA_TOT 16384

__device__ float d_xb[BN_TOT*HD];
__device__ float d_A [BN_TOT*HD];   // [t][b][j]
__device__ float d_Y8[NA_TOT*8];
__device__ float d_ge[NB*HD];
__device__ __align__(16) unsigned short d_adjh[NB*1024*1024];  // adj in bf16
__device__ __align__(16) unsigned short d_gh[BN_TOT*HD];       // g in bf16, [b][node][hd]

__device__ __forceinline__ void ffma2(float2 &c, const float2 a, const float2 b) {
    asm("fma.rn.f32x2 %0, %1, %2, %0;"
        : "+l"(reinterpret_cast<unsigned long long&>(c))
        : "l"(reinterpret_cast<const unsigned long long&>(a)),
          "l"(reinterpret_cast<const unsigned long long&>(b)));
}
__device__ __forceinline__ uint32_t smem_u32(const void* p) {
    uint32_t a;
    asm("{ .reg .u64 t; cvta.to.shared.u64 t, %1; cvt.u32.u64 %0, t; }" : "=r"(a) : "l"(p));
    return a;
}
__device__ __forceinline__ void cp16(uint32_t dst, const void* src) {
    asm volatile("cp.async.cg.shared.global [%0], [%1], 16;" :: "r"(dst), "l"(src));
}
__device__ __forceinline__ void ldm_x4(uint32_t* r, uint32_t addr) {
    asm volatile("ldmatrix.sync.aligned.m8n8.x4.shared.b16 {%0,%1,%2,%3}, [%4];"
        : "=r"(r[0]), "=r"(r[1]), "=r"(r[2]), "=r"(r[3]) : "r"(addr));
}
__device__ __forceinline__ void ldm_x4t(uint32_t* r, uint32_t addr) {
    asm volatile("ldmatrix.sync.aligned.m8n8.x4.trans.shared.b16 {%0,%1,%2,%3}, [%4];"
        : "=r"(r[0]), "=r"(r[1]), "=r"(r[2]), "=r"(r[3]) : "r"(addr));
}
__device__ __forceinline__ void mma_bf16(float* d, const uint32_t* a, const uint32_t* b) {
    asm volatile("mma.sync.aligned.m16n8k16.row.col.f32.bf16.bf16.f32 "
        "{%0,%1,%2,%3}, {%4,%5,%6,%7}, {%8,%9}, {%0,%1,%2,%3};"
        : "+f"(d[0]), "+f"(d[1]), "+f"(d[2]), "+f"(d[3])
        : "r"(a[0]), "r"(a[1]), "r"(a[2]), "r"(a[3]), "r"(b[0]), "r"(b[1]));
}
__device__ __forceinline__ float ftanh(float x) {
    float e = __expf(2.0f * x);
    return 1.0f - __fdividef(2.0f, e + 1.0f);
}
__device__ __forceinline__ uint32_t pack_bf2(float x, float y) {
    __nv_bfloat162 p = __floats2bfloat162_rn(x, y);
    return *reinterpret_cast<uint32_t*>(&p);
}

// ---- K0: adj fp32 -> bf16 ----
__global__ void k_cvt(const float* __restrict__ adj) {
    int idx = blockIdx.x * 256 + threadIdx.x;    // 4M threads, 8 floats each
    const float4* s = (const float4*)adj + (size_t)idx * 2;
    float4 a = s[0], b = s[1];
    uint4 o;
    o.x = pack_bf2(a.x, a.y);
    o.y = pack_bf2(a.z, a.w);
    o.z = pack_bf2(b.x, b.y);
    o.w = pack_bf2(b.z, b.w);
    ((uint4*)d_adjh)[idx] = o;
}

// ---- K1: xb = x@W1^T + b1 + b2 ; h = relu(xb) ----
__global__ void k_init(const float* __restrict__ x, const float* __restrict__ W1,
                       const float* __restrict__ b1, const float* __restrict__ b2,
                       float* __restrict__ hout) {
    int idx = blockIdx.x * 256 + threadIdx.x;
    int i = idx >> 6, j = idx & 63;
    float2 xv = ((const float2*)x)[i];
    float v = fmaf(xv.x, W1[2*j], fmaf(xv.y, W1[2*j+1], b1[j])) + b2[j];
    d_xb[idx] = v;
    hout[idx] = fmaxf(v, 0.f);
}

// ---- K2: mode0 -> d_gh[b][node][hd] = bf16(in@W^T); mode1 -> d_A[t][b][j] = in@W^T + bA+bB ----
__global__ void __launch_bounds__(128) k_small(const float* __restrict__ in,
        const float* __restrict__ W, const float* __restrict__ bA,
        const float* __restrict__ bB, int mode) {
    __shared__ float hsT[64][36];
    __shared__ float Wt[64][68];
    __shared__ float bs[64];
    int tid = threadIdx.x;
    int i0 = blockIdx.x * 32;
    for (int idx = tid; idx < 4096; idx += 128)
        Wt[idx & 63][idx >> 6] = W[idx];
    if (mode && tid < 64) bs[tid] = bA[tid] + bB[tid];
    #pragma unroll
    for (int u = 0; u < 4; ++u) {
        int f = tid + 128 * u;
        int r = f >> 4, kc = (f & 15) * 4;
        float4 v = *(const float4*)&in[(i0 + r) * 64 + kc];
        hsT[kc+0][r] = v.x; hsT[kc+1][r] = v.y; hsT[kc+2][r] = v.z; hsT[kc+3][r] = v.w;
    }
    __syncthreads();
    int r4 = (tid & 7) * 4, j4 = (tid >> 3) * 4;
    float2 acc[4][2];
    #pragma unroll
    for (int rr = 0; rr < 4; ++rr) { acc[rr][0] = make_float2(0,0); acc[rr][1] = make_float2(0,0); }
    #pragma unroll 8
    for (int k = 0; k < 64; ++k) {
        float4 a = *(const float4*)&hsT[k][r4];
        float4 w = *(const float4*)&Wt[k][j4];
        float2 w01 = make_float2(w.x, w.y), w23 = make_float2(w.z, w.w);
        ffma2(acc[0][0], w01, make_float2(a.x, a.x));
        ffma2(acc[0][1], w23, make_float2(a.x, a.x));
        ffma2(acc[1][0], w01, make_float2(a.y, a.y));
        ffma2(acc[1][1], w23, make_float2(a.y, a.y));
        ffma2(acc[2][0], w01, make_float2(a.z, a.z));
        ffma2(acc[2][1], w23, make_float2(a.z, a.z));
        ffma2(acc[3][0], w01, make_float2(a.w, a.w));
        ffma2(acc[3][1], w23, make_float2(a.w, a.w));
    }
    int bb = i0 >> 10, rloc = (i0 & 1023) + r4;
    if (mode == 0) {
        #pragma unroll
        for (int rr = 0; rr < 4; ++rr) {
            uint2 v;
            v.x = pack_bf2(acc[rr][0].x, acc[rr][0].y);
            v.y = pack_bf2(acc[rr][1].x, acc[rr][1].y);
            *(uint2*)&d_gh[(bb * 1024 + rloc + rr) * 64 + j4] = v;
        }
    } else {
        #pragma unroll
        for (int rr = 0; rr < 4; ++rr) {
            float4 v;
            v.x = acc[rr][0].x + bs[j4+0];
            v.y = acc[rr][0].y + bs[j4+1];
            v.z = acc[rr][1].x + bs[j4+2];
            v.w = acc[rr][1].y + bs[j4+3];
            *(float4*)&d_A[((rloc + rr) * 32 + bb) * 64 + j4] = v;
        }
    }
}

// ---- K3: h = relu(xb + adj@g) via bf16 mma.sync + ldmatrix ----
#define AP 72                      // bf16 elems per A row (144 B, conflict-free ldmatrix)
#define BP 72
#define ASZB (128*AP*2)            // 18432 B per A buffer
#define BSZB (64*BP*2)             // 9216 B per B buffer
#define GSMB (2*ASZB + 2*BSZB)     // 55296 B

__global__ void __launch_bounds__(128, 2) k_gnn_bf(float* __restrict__ hout) {
    extern __shared__ char smh[];
    uint32_t sA = smem_u32(smh);
    uint32_t sB = sA + 2 * ASZB;
    int tid = threadIdx.x, lane = tid & 31, w = tid >> 5;
    int mt = blockIdx.x, bb = blockIdx.y;
    const char* Abase = (const char*)d_adjh + ((size_t)bb << 21) + ((size_t)mt << 18);
    const char* Bbase = (const char*)d_gh + ((size_t)bb << 17);

    float acc[2][8][4];
    #pragma unroll
    for (int m = 0; m < 2; ++m)
        #pragma unroll
        for (int j = 0; j < 8; ++j)
            #pragma unroll
            for (int q = 0; q < 4; ++q) acc[m][j][q] = 0.f;

    auto loadA = [&](int buf, int kt) {
        uint32_t dst = sA + buf * ASZB;
        #pragma unroll
        for (int u = 0; u < 8; ++u) {
            int idx = tid + 128 * u;               // 0..1023
            int row = idx >> 3, c = idx & 7;
            cp16(dst + row * 144 + c * 16, Abase + (size_t)row * 2048 + kt * 128 + c * 16);
        }
    };
    auto loadB = [&](int buf, int kt) {
        uint32_t dst = sB + buf * BSZB;
        #pragma unroll
        for (int u = 0; u < 4; ++u) {
            int idx = tid + 128 * u;               // 0..511
            int row = idx >> 3, c = idx & 7;
            cp16(dst + row * 144 + c * 16, Bbase + (size_t)(kt * 64 + row) * 128 + c * 16);
        }
    };

    loadA(0, 0); loadB(0, 0);
    asm volatile("cp.async.commit_group;");

    for (int kt = 0; kt < 16; ++kt) {
        int buf = kt & 1;
        if (kt + 1 < 16) {
            loadA(buf ^ 1, kt + 1);
            loadB(buf ^ 1, kt + 1);
            asm volatile("cp.async.commit_group;");
            asm volatile("cp.async.wait_group 1;" ::: "memory");
        } else {
            asm volatile("cp.async.wait_group 0;" ::: "memory");
        }
        __syncthreads();
        uint32_t a0 = sA + buf * ASZB + (32 * w) * 144;
        uint32_t b0 = sB + buf * BSZB;
        int arow = lane & 15, acol = (lane >> 4) * 8;
        int q = lane >> 3;
        int brow = (lane & 7) + 8 * (q & 1);
        int bcol = 8 * (q >> 1);
        #pragma unroll
        for (int ks = 0; ks < 4; ++ks) {
            uint32_t a[2][4];
            #pragma unroll
            for (int m = 0; m < 2; ++m)
                ldm_x4(a[m], a0 + (m * 16 + arow) * 144 + (ks * 16 + acol) * 2);
            uint32_t bf[8][2];
            #pragma unroll
            for (int np = 0; np < 4; ++np) {
                uint32_t t4[4];
                ldm_x4t(t4, b0 + (ks * 16 + brow) * 144 + (np * 16 + bcol) * 2);
                bf[2*np][0] = t4[0]; bf[2*np][1] = t4[1];
                bf[2*np+1][0] = t4[2]; bf[2*np+1][1] = t4[3];
            }
            #pragma unroll
            for (int m = 0; m < 2; ++m)
                #pragma unroll
                for (int j = 0; j < 8; ++j)
                    mma_bf16(acc[m][j], a[m], bf[j]);
        }
        __syncthreads();
    }

    int r = lane >> 2, c2 = (lane & 3) * 2;
    size_t row0 = ((size_t)bb << 10) + ((size_t)mt << 7) + 32 * w;
    #pragma unroll
    for (int m = 0; m < 2; ++m) {
        #pragma unroll
        for (int j = 0; j < 8; ++j) {
            int col = 8 * j + c2;
            size_t o0 = (row0 + m * 16 + r) * 64 + col;
            float2 xb0 = *(const float2*)&d_xb[o0];
            float2 h0;
            h0.x = fmaxf(xb0.x + acc[m][j][0], 0.f);
            h0.y = fmaxf(xb0.y + acc[m][j][1], 0.f);
            *(float2*)&hout[o0] = h0;
            size_t o1 = (row0 + m * 16 + r + 8) * 64 + col;
            float2 xb1 = *(const float2*)&d_xb[o1];
            float2 h1;
            h1.x = fmaxf(xb1.x + acc[m][j][2], 0.f);
            h1.y = fmaxf(xb1.y + acc[m][j][3], 0.f);
            *(float2*)&hout[o1] = h1;
        }
    }
}

// ---- K4: pipelined scan, 1 barrier/step ----
__global__ void __launch_bounds__(224, 1) k_scan2(const float* __restrict__ Whh0,
        const float* __restrict__ Wih1, const float* __restrict__ Whh1,
        const float* __restrict__ bih1, const float* __restrict__ bhh1,
        const float* __restrict__ Wt6, const float* __restrict__ bt6) {
    __shared__ float S[4][64];
    __shared__ float Abuf[8][64];
    __shared__ float bsum[64];
    int b = blockIdx.x, tid = threadIdx.x;
    for (int i = tid; i < 256; i += 224) ((float*)S)[i] = 0.f;
    if (tid < 64) bsum[tid] = bih1[tid] + bhh1[tid];

    float2 w[32];
    int part = 0, j0 = 0;
    float2 avreg = make_float2(0.f, 0.f);
    if (tid < 64) {
        int lane = tid & 31, wd = tid >> 5;
        int jp = wd * 16 + (lane & 15); part = lane >> 4; j0 = jp * 2;
        #pragma unroll
        for (int kk = 0; kk < 32; ++kk) {
            int k = part * 32 + kk;
            w[kk] = make_float2(Whh0[j0 * 64 + k], Whh0[(j0 + 1) * 64 + k]);
        }
    } else if (tid < 192) {
        int bt = tid - 64, lane = bt & 31, wd = bt >> 5;
        int jp = wd * 8 + (lane & 7); part = lane >> 3; j0 = jp * 2;
        #pragma unroll
        for (int kk = 0; kk < 32; ++kk) {
            int k = part * 32 + kk;
            const float* Ws = (k < 64) ? Wih1 : Whh1;
            int ko = k & 63;
            w[kk] = make_float2(Ws[j0 * 64 + ko], Ws[(j0 + 1) * 64 + ko]);
        }
    } else {
        int lane = tid - 192;
        #pragma unroll
        for (int u = 0; u < 4; ++u)
            *(float2*)&Abuf[u][lane * 2] = *(const float2*)&d_A[(u * 32 + b) * 64 + lane * 2];
        avreg = *(const float2*)&d_A[(4 * 32 + b) * 64 + lane * 2];
    }
    __syncthreads();

    int pc = 0;
    for (int t = 0; t <= 1024; ++t) {
        if (tid < 64) {
            if (t < 1024) {
                float2 a0 = {0,0}, a1 = {0,0}, a2 = {0,0}, a3 = {0,0};
                const float* c = &S[pc][part * 32];
                #pragma unroll
                for (int k4 = 0; k4 < 8; ++k4) {
                    float4 cv = *(const float4*)(c + k4 * 4);
                    ffma2(a0, w[k4*4+0], make_float2(cv.x, cv.x));
                    ffma2(a1, w[k4*4+1], make_float2(cv.y, cv.y));
                    ffma2(a2, w[k4*4+2], make_float2(cv.z, cv.z));
                    ffma2(a3, w[k4*4+3], make_float2(cv.w, cv.w));
                }
                float2 s;
                s.x = (a0.x + a1.x) + (a2.x + a3.x);
                s.y = (a0.y + a1.y) + (a2.y + a3.y);
                s.x += __shfl_xor_sync(0xffffffffu, s.x, 16);
                s.y += __shfl_xor_sync(0xffffffffu, s.y, 16);
                if (part == 0) {
                    float2 at = *(const float2*)&Abuf[t & 7][j0];
                    float2 rr;
                    rr.x = ftanh(s.x + at.x);
                    rr.y = ftanh(s.y + at.y);
                    *(float2*)&S[pc ^ 1][j0] = rr;
                }
            }
        } else if (tid < 192) {
            float2 a0 = {0,0}, a1 = {0,0}, a2 = {0,0}, a3 = {0,0};
            const float* c = (part < 2) ? &S[pc][(part & 1) * 32]
                                        : &S[2 + pc][(part & 1) * 32];
            #pragma unroll
            for (int k4 = 0; k4 < 8; ++k4) {
                float4 cv = *(const float4*)(c + k4 * 4);
                ffma2(a0, w[k4*4+0], make_float2(cv.x, cv.x));
                ffma2(a1, w[k4*4+1], make_float2(cv.y, cv.y));
                ffma2(a2, w[k4*4+2], make_float2(cv.z, cv.z));
                ffma2(a3, w[k4*4+3], make_float2(cv.w, cv.w));
            }
            float2 s;
            s.x = (a0.x + a1.x) + (a2.x + a3.x);
            s.y = (a0.y + a1.y) + (a2.y + a3.y);
            s.x += __shfl_xor_sync(0xffffffffu, s.x, 8);
            s.y += __shfl_xor_sync(0xffffffffu, s.y, 8);
            s.x += __shfl_xor_sync(0xffffffffu, s.x, 16);
            s.y += __shfl_xor_sync(0xffffffffu, s.y, 16);
            if (part == 0) {
                float2 bv = *(const float2*)&bsum[j0];
                float2 rr;
                if (t == 0) { rr.x = 0.f; rr.y = 0.f; }
                else { rr.x = ftanh(s.x + bv.x); rr.y = ftanh(s.y + bv.y); }
                *(float2*)&S[2 + (pc ^ 1)][j0] = rr;
            }
        } else {
            int lane = tid - 192;
            *(float2*)&Abuf[(t + 4) & 7][lane * 2] = avreg;
            int tt = t + 5;
            if (tt < 1024)
                avreg = *(const float2*)&d_A[(tt * 32 + b) * 64 + lane * 2];
        }
        __syncthreads();
        pc ^= 1;
    }
    if (tid < 64) {
        int j = tid;
        float acc = bt6[j];
        const float* cf = S[2 + pc];
        #pragma unroll 8
        for (int k = 0; k < 64; ++k) acc = fmaf(cf[k], Wt6[j * 64 + k], acc);
        d_ge[b * 64 + j] = acc;
    }
}

// ---- K5: gather + R + Y8 ----
__global__ void k_r(const int* __restrict__ label, const int* __restrict__ actions,
                    const float* __restrict__ x, float* __restrict__ Rout) {
    int a = blockIdx.x * 256 + threadIdx.x;
    int b = a >> 9;
    int i0 = actions[2 * a], i1 = actions[2 * a + 1];
    const int* lb = label + (b << 10);
    int a0 = lb[i0], a1 = lb[i1];
    int li = lb[(i0 + 1023) & 1023], ri = lb[(i1 + 1) & 1023];
    int off = b << 10;
    const float2* xv = (const float2*)x;
    float2 y0 = xv[a0 + off], y1 = xv[a1 + off], y2 = xv[li + off], y3 = xv[ri + off];
    float d02x = y0.x - y2.x, d02y = y0.y - y2.y;
    float d13x = y1.x - y3.x, d13y = y1.y - y3.y;
    float d12x = y1.x - y2.x, d12y = y1.y - y2.y;
    float d03x = y0.x - y3.x, d03y = y0.y - y3.y;
    float R = sqrtf(fmaf(d02x, d02x, d02y * d02y)) + sqrtf(fmaf(d13x, d13x, d13y * d13y))
            - sqrtf(fmaf(d12x, d12x, d12y * d12y)) - sqrtf(fmaf(d03x, d03x, d03y * d03y));
    Rout[a] = R;
    float4* Y = (float4*)(d_Y8 + a * 8);
    Y[0] = make_float4(y0.x, y0.y, y1.x, y1.y);
    Y[1] = make_float4(y2.x, y2.y, y3.x, y3.y);
}

// ---- K6: feat + Q ----
__global__ void k_q(const float* __restrict__ WL, const float* __restrict__ bL,
                    const float* __restrict__ Wt5, const float* __restrict__ bt5,
                    const float* __restrict__ R, float* __restrict__ Q) {
    __shared__ float ges[64], WLs[512], bLs[64], w5[65];
    int b = blockIdx.x, a = threadIdx.x;
    if (a < 64) { ges[a] = d_ge[b * 64 + a]; bLs[a] = bL[a]; w5[a] = Wt5[a]; }
    if (a == 64) w5[64] = Wt5[64];
    WLs[a] = WL[a];
    __syncthreads();
    int ba = b * 512 + a;
    float4 y0 = *(const float4*)&d_Y8[ba * 8];
    float4 y1 = *(const float4*)&d_Y8[ba * 8 + 4];
    float y[8] = {y0.x, y0.y, y0.z, y0.w, y1.x, y1.y, y1.z, y1.w};
    float q = 0.f;
    #pragma unroll 8
    for (int j = 0; j < 64; ++j) {
        float f = ges[j] + bLs[j];
        #pragma unroll
        for (int m = 0; m < 8; ++m) f = fmaf(y[m], WLs[j * 8 + m], f);
        q = fmaf(fmaxf(f, 0.f), w5[j], q);
    }
    Q[ba] = fmaf(R[ba], w5[64], q) + bt5[0];
}

extern "C" void kernel_launch(void* const* d_in, const int* in_sizes, int n_in,
                              void* d_out, int out_size) {
    const float* adj  = (const float*)d_in[0];
    const float* x    = (const float*)d_in[1];
    const int*  label = (const int*)  d_in[2];
    const int*  acts  = (const int*)  d_in[3];
    const float* W1   = (const float*)d_in[4];
    const float* b1   = (const float*)d_in[5];
    const float* W2   = (const float*)d_in[6];
    const float* b2   = (const float*)d_in[7];
    const float* Wih0 = (const float*)d_in[8];
    const float* bih0 = (const float*)d_in[9];
    const float* Whh0 = (const float*)d_in[10];
    const float* bhh0 = (const float*)d_in[11];
    const float* Wih1 = (const float*)d_in[12];
    const float* bih1 = (const float*)d_in[13];
    const float* Whh1 = (const float*)d_in[14];
    const float* bhh1 = (const float*)d_in[15];
    const float* Wt6  = (const float*)d_in[16];
    const float* bt6  = (const float*)d_in[17];
    const float* WL   = (const float*)d_in[18];
    const float* bL   = (const float*)d_in[19];
    const float* Wt5  = (const float*)d_in[20];
    const float* bt5  = (const float*)d_in[21];

    float* out  = (float*)d_out;
    float* Rout = out;
    float* hout = out + 16384;
    float* Qout = out + 16384 + BN_TOT * HD;

    cudaFuncSetAttribute(k_gnn_bf, cudaFuncAttributeMaxDynamicSharedMemorySize, GSMB);

    k_cvt<<<16384, 256>>>(adj);                               // 1
    k_init<<<8192, 256>>>(x, W1, b1, b2, hout);               // 2
    k_small<<<1024, 128>>>(hout, W2, b2, b2, 0);              // 3
    k_gnn_bf<<<dim3(8, 32), 128, GSMB>>>(hout);               // 4
    k_small<<<1024, 128>>>(hout, W2, b2, b2, 0);              // 5
    k_gnn_bf<<<dim3(8, 32), 128, GSMB>>>(hout);               // 6  <- ncu slot
    k_small<<<1024, 128>>>(hout, Wih0, bih0, bhh0, 1);        // 7
    k_scan2<<<32, 224>>>(Whh0, Wih1, Whh1, bih1, bhh1, Wt6, bt6);  // 8
    k_r<<<64, 256>>>(label, acts, x, Rout);                   // 9
    k_q<<<32, 512>>>(WL, bL, Wt5, bt5, Rout, Qout);           // 10
}